// round 3
// baseline (speedup 1.0000x reference)
#include <cuda_runtime.h>

// InputDefenseLayer: y[b,0,c] = clip(x[b,0,c]); y[b,t,c] = 0.25*clip(x[b,t,c]) + 0.75*y[b,t-1,c]
//
// Chunked-scan with halo warmup: 0.75^128 ~ 1e-16, so a 128-step warmup makes each
// chunk's recurrence exact to fp32 regardless of init. 8 chunks x 64 batches = 512
// independent units; each unit = 64 threads, one float4 (4 channels) per thread.

static constexpr int B_DIM  = 64;
static constexpr int T_DIM  = 2048;
static constexpr int C_DIM  = 256;
static constexpr int C4     = C_DIM / 4;     // 64 float4 lanes per (b,t) row

static constexpr int CHUNK  = 256;           // stored timesteps per unit
static constexpr int HALO   = 128;           // warmup steps (0.75^128 ~ 1.1e-16)
static constexpr int NCHUNK = T_DIM / CHUNK; // 8

static constexpr float A_COEF = 0.25f;
static constexpr float B_COEF = 0.75f;
static constexpr float CLIP_MIN = -3.5f;
static constexpr float CLIP_MAX =  3.5f;

__device__ __forceinline__ float4 clip4(float4 v) {
    v.x = fminf(fmaxf(v.x, CLIP_MIN), CLIP_MAX);
    v.y = fminf(fmaxf(v.y, CLIP_MIN), CLIP_MAX);
    v.z = fminf(fmaxf(v.z, CLIP_MIN), CLIP_MAX);
    v.w = fminf(fmaxf(v.w, CLIP_MIN), CLIP_MAX);
    return v;
}

__device__ __forceinline__ float4 ema4(float4 s, float4 x) {
    s.x = fmaf(A_COEF, x.x, B_COEF * s.x);
    s.y = fmaf(A_COEF, x.y, B_COEF * s.y);
    s.z = fmaf(A_COEF, x.z, B_COEF * s.z);
    s.w = fmaf(A_COEF, x.w, B_COEF * s.w);
    return s;
}

__global__ __launch_bounds__(64)
void ema_scan_kernel(const float4* __restrict__ x, float4* __restrict__ y) {
    const int unit  = blockIdx.x;           // 0 .. B_DIM*NCHUNK-1
    const int b     = unit / NCHUNK;
    const int chunk = unit - b * NCHUNK;
    const int lane  = threadIdx.x;          // 0 .. 63 (float4 lane within channel row)

    const float4* __restrict__ xi = x + (size_t)b * T_DIM * C4 + lane;
    float4*       __restrict__ yo = y + (size_t)b * T_DIM * C4 + lane;

    const int t0 = chunk * CHUNK;                    // first stored timestep
    const int ts = (chunk == 0) ? 0 : (t0 - HALO);   // first loaded timestep

    // Init: exact for chunk 0 (s_0 = clip(x_0)); for others any bounded init works,
    // error decays by 0.75^HALO before the first store.
    float4 s = clip4(xi[(size_t)ts * C4]);
    if (chunk == 0) {
        yo[0] = s;
    }

    // Halo warmup (empty for chunk 0). Loads are independent of s, so the
    // unrolled body batches 8 outstanding LDG.128 per thread.
    #pragma unroll 8
    for (int t = ts + 1; t < t0; ++t) {
        s = ema4(s, clip4(xi[(size_t)t * C4]));
    }

    // Main stored region.
    const int tb = (chunk == 0) ? 1 : t0;
    #pragma unroll 8
    for (int t = tb; t < t0 + CHUNK; ++t) {
        s = ema4(s, clip4(xi[(size_t)t * C4]));
        yo[(size_t)t * C4] = s;
    }
}

extern "C" void kernel_launch(void* const* d_in, const int* in_sizes, int n_in,
                              void* d_out, int out_size) {
    const float4* x = (const float4*)d_in[0];
    float4*       y = (float4*)d_out;
    ema_scan_kernel<<<B_DIM * NCHUNK, 64>>>(x, y);
}

// round 4
// speedup vs baseline: 1.0194x; 1.0194x over previous
#include <cuda_runtime.h>

// InputDefenseLayer: y[b,0,c] = clip(x[b,0,c]); y[b,t,c] = 0.25*clip(x[b,t,c]) + 0.75*y[b,t-1,c]
//
// Chunked-scan with halo warmup: 0.75^128 ~ 1e-16, so a 128-step warmup makes each
// chunk's recurrence exact to fp32 regardless of init. 8 chunks x 64 batches = 512
// independent units; each unit = 64 threads, one float4 (4 channels) per thread.

static constexpr int B_DIM  = 64;
static constexpr int T_DIM  = 2048;
static constexpr int C_DIM  = 256;
static constexpr int C4     = C_DIM / 4;     // 64 float4 lanes per (b,t) row

static constexpr int CHUNK  = 256;           // stored timesteps per unit
static constexpr int HALO   = 128;           // warmup steps (0.75^128 ~ 1.1e-16)
static constexpr int NCHUNK = T_DIM / CHUNK; // 8

static constexpr float A_COEF = 0.25f;
static constexpr float B_COEF = 0.75f;
static constexpr float CLIP_MIN = -3.5f;
static constexpr float CLIP_MAX =  3.5f;

__device__ __forceinline__ float4 clip4(float4 v) {
    v.x = fminf(fmaxf(v.x, CLIP_MIN), CLIP_MAX);
    v.y = fminf(fmaxf(v.y, CLIP_MIN), CLIP_MAX);
    v.z = fminf(fmaxf(v.z, CLIP_MIN), CLIP_MAX);
    v.w = fminf(fmaxf(v.w, CLIP_MIN), CLIP_MAX);
    return v;
}

__device__ __forceinline__ float4 ema4(float4 s, float4 x) {
    s.x = fmaf(A_COEF, x.x, B_COEF * s.x);
    s.y = fmaf(A_COEF, x.y, B_COEF * s.y);
    s.z = fmaf(A_COEF, x.z, B_COEF * s.z);
    s.w = fmaf(A_COEF, x.w, B_COEF * s.w);
    return s;
}

__global__ __launch_bounds__(64)
void ema_scan_kernel(const float4* __restrict__ x, float4* __restrict__ y) {
    const int unit  = blockIdx.x;           // 0 .. B_DIM*NCHUNK-1
    const int b     = unit / NCHUNK;
    const int chunk = unit - b * NCHUNK;
    const int lane  = threadIdx.x;          // 0 .. 63 (float4 lane within channel row)

    const float4* __restrict__ xi = x + (size_t)b * T_DIM * C4 + lane;
    float4*       __restrict__ yo = y + (size_t)b * T_DIM * C4 + lane;

    const int t0 = chunk * CHUNK;                    // first stored timestep
    const int ts = (chunk == 0) ? 0 : (t0 - HALO);   // first loaded timestep

    // Init: exact for chunk 0 (s_0 = clip(x_0)); for others any bounded init works,
    // error decays by 0.75^HALO before the first store.
    float4 s = clip4(xi[(size_t)ts * C4]);
    if (chunk == 0) {
        yo[0] = s;
    }

    // Halo warmup (empty for chunk 0). Loads are independent of s, so the
    // unrolled body batches 8 outstanding LDG.128 per thread.
    #pragma unroll 8
    for (int t = ts + 1; t < t0; ++t) {
        s = ema4(s, clip4(xi[(size_t)t * C4]));
    }

    // Main stored region.
    const int tb = (chunk == 0) ? 1 : t0;
    #pragma unroll 8
    for (int t = tb; t < t0 + CHUNK; ++t) {
        s = ema4(s, clip4(xi[(size_t)t * C4]));
        yo[(size_t)t * C4] = s;
    }
}

extern "C" void kernel_launch(void* const* d_in, const int* in_sizes, int n_in,
                              void* d_out, int out_size) {
    const float4* x = (const float4*)d_in[0];
    float4*       y = (float4*)d_out;
    ema_scan_kernel<<<B_DIM * NCHUNK, 64>>>(x, y);
}